// round 5
// baseline (speedup 1.0000x reference)
#include <cuda_runtime.h>
#include <cuda_bf16.h>
#include <math.h>
#include <stdint.h>

// Problem constants
#define BB 32
#define TT 64
#define HH 1024
#define EE 512
#define VV 32000
#define NROWS (BB * TT)          // 2048
#define KIN  (EE + HH)           // 1536
#define G3H  (3 * HH)            // 3072
static const size_t BTV = (size_t)BB * TT * VV;  // 65,536,000

// ---------------- device scratch (static module allocations; no cudaMalloc) ----
__device__ float g_A0[NROWS * KIN];        // dec_in  [2048, 1536]
__device__ float g_gx0[NROWS * G3H];       // x-gates layer0 [2048, 3072]
__device__ float g_seq[NROWS * HH];        // h2 per (b,t)   [2048, 1024]
__device__ float g_h1[2][BB * HH];         // ping-pong hidden, layer 0
__device__ float g_h2[2][BB * HH];         // ping-pong hidden, layer 1
__device__ int   g_tok[NROWS];             // normalized tokens (int64/int32 safe)

// ---------------- helpers ------------------------------------------------------
__device__ __forceinline__ uint32_t f2tf(float x) {
    uint32_t u;
    asm("cvt.rna.tf32.f32 %0, %1;" : "=r"(u) : "f"(x));
    return u;
}
__device__ __forceinline__ float f2tff(float x) { return __uint_as_float(f2tf(x)); }

__device__ __forceinline__ void mma_tf32(float c[4], const uint32_t a[4],
                                         uint32_t b0, uint32_t b1) {
    asm volatile(
        "mma.sync.aligned.m16n8k8.row.col.f32.tf32.tf32.f32 "
        "{%0,%1,%2,%3}, {%4,%5,%6,%7}, {%8,%9}, {%0,%1,%2,%3};\n"
        : "+f"(c[0]), "+f"(c[1]), "+f"(c[2]), "+f"(c[3])
        : "r"(a[0]), "r"(a[1]), "r"(a[2]), "r"(a[3]), "r"(b0), "r"(b1));
}

__device__ __forceinline__ float sigm(float x) { return 1.0f / (1.0f + expf(-x)); }

// ---------------- token dtype detect + normalize -------------------------------
// X may be int64 (declared) or int32 (JAX x64 off). If int64, every odd 32-bit
// word is 0 (tokens < 2^31). Scanning words [1..2047] is in-bounds either way.
__global__ void detect_tokens(const int* __restrict__ Xw) {
    __shared__ int flag;
    int tid = threadIdx.x;
    if (tid == 0) flag = 0;
    __syncthreads();
    if (Xw[2 * tid + 1] != 0) atomicOr(&flag, 1);
    __syncthreads();
    bool is64 = (flag == 0);
    for (int i = tid; i < NROWS; i += 1024)
        g_tok[i] = is64 ? Xw[2 * i] : Xw[i];
}

// ---------------- prep: build dec_in, init hidden ------------------------------
__global__ void prep_kernel(const float* __restrict__ h0, const float* __restrict__ emb) {
    int idx = blockIdx.x * blockDim.x + threadIdx.x;
    if (idx < BB * HH) {
        g_h1[0][idx] = h0[idx];                 // h0[0]
        g_h2[0][idx] = h0[BB * HH + idx];       // h0[1]
    }
    if (idx >= NROWS * KIN) return;
    int n = idx / KIN;
    int k = idx - n * KIN;
    float v;
    if (k < EE) {
        v = emb[(size_t)g_tok[n] * EE + k];
    } else {
        int b = n >> 6;                          // n = b*T + t
        v = h0[BB * HH + b * HH + (k - EE)];     // context = h0[1][b]
    }
    g_A0[idx] = v;
}

// ---------------- big tf32 GEMM: C[M,N] = A[M,K] @ B[K,N] + bias ---------------
// sel==0: A=g_A0, C=g_gx0 (gx0).  sel==1: A=g_seq, C=Cext (logits -> d_out).
// Tiles: BM=128, BN=256, BK=16, 512 threads (16 warps, 4x4 warp grid, 32x64/warp)
__global__ __launch_bounds__(512, 1)
void gemm_tf32(int sel, const float* __restrict__ Bm, const float* __restrict__ bias,
               float* __restrict__ Cext, int M, int N, int K) {
    const float* A = sel ? g_seq : g_A0;
    float* C = sel ? Cext : g_gx0;

    const int BM = 128, BN = 256;
    __shared__ float As[16][BM + 4];   // transposed: As[k][m], tf32-rounded
    __shared__ float Bs[16][BN + 4];   // Bs[k][n],  tf32-rounded

    int tid = threadIdx.x;
    int warp = tid >> 5, lane = tid & 31;
    int wm = warp >> 2, wn = warp & 3;           // 4x4 warp grid
    int lg = lane >> 2, lt = lane & 3;

    int mtiles = M / BM;
    int bm = blockIdx.x % mtiles;                // M fast-varying -> B-tile L2 reuse
    int bn = blockIdx.x / mtiles;
    int m0 = bm * BM, n0 = bn * BN;

    float acc[2][8][4];
#pragma unroll
    for (int a = 0; a < 2; a++)
#pragma unroll
        for (int b = 0; b < 8; b++)
#pragma unroll
            for (int c = 0; c < 4; c++) acc[a][b][c] = 0.0f;

    for (int k0 = 0; k0 < K; k0 += 16) {
        // stage A tile 128x16 (1 float4 / thread), transposed + tf32 rounding
        {
            int m = tid >> 2;
            int kq = (tid & 3) << 2;
            const float4 v = *reinterpret_cast<const float4*>(
                A + (size_t)(m0 + m) * K + k0 + kq);
            As[kq + 0][m] = f2tff(v.x);
            As[kq + 1][m] = f2tff(v.y);
            As[kq + 2][m] = f2tff(v.z);
            As[kq + 3][m] = f2tff(v.w);
        }
        // stage B tile 16x256 (2 float4 / thread)
#pragma unroll
        for (int p = 0; p < 2; p++) {
            int i = tid + (p << 9);
            int kr = i >> 6;
            int nc = (i & 63) << 2;
            const float4 v = *reinterpret_cast<const float4*>(
                Bm + (size_t)(k0 + kr) * N + n0 + nc);
            Bs[kr][nc + 0] = f2tff(v.x);
            Bs[kr][nc + 1] = f2tff(v.y);
            Bs[kr][nc + 2] = f2tff(v.z);
            Bs[kr][nc + 3] = f2tff(v.w);
        }
        __syncthreads();

#pragma unroll
        for (int kk = 0; kk < 16; kk += 8) {
            uint32_t aF[2][4];
#pragma unroll
            for (int mt = 0; mt < 2; mt++) {
                int mr = wm * 32 + mt * 16 + lg;
                aF[mt][0] = __float_as_uint(As[kk + lt][mr]);
                aF[mt][1] = __float_as_uint(As[kk + lt][mr + 8]);
                aF[mt][2] = __float_as_uint(As[kk + lt + 4][mr]);
                aF[mt][3] = __float_as_uint(As[kk + lt + 4][mr + 8]);
            }
#pragma unroll
            for (int nt = 0; nt < 8; nt++) {
                int nc2 = wn * 64 + nt * 8 + lg;
                uint32_t b0r = __float_as_uint(Bs[kk + lt][nc2]);
                uint32_t b1r = __float_as_uint(Bs[kk + 4 + lt][nc2]);
                mma_tf32(acc[0][nt], aF[0], b0r, b1r);
                mma_tf32(acc[1][nt], aF[1], b0r, b1r);
            }
        }
        __syncthreads();
    }

    // epilogue: bias add + float2 stores (sector-complete rows)
#pragma unroll
    for (int mt = 0; mt < 2; mt++) {
#pragma unroll
        for (int nt = 0; nt < 8; nt++) {
            int r = m0 + wm * 32 + mt * 16 + lg;
            int c = n0 + wn * 64 + nt * 8 + lt * 2;
            float bv0 = bias[c], bv1 = bias[c + 1];
            float2 v01 = make_float2(acc[mt][nt][0] + bv0, acc[mt][nt][1] + bv1);
            *reinterpret_cast<float2*>(C + (size_t)r * N + c) = v01;
            float2 v23 = make_float2(acc[mt][nt][2] + bv0, acc[mt][nt][3] + bv1);
            *reinterpret_cast<float2*>(C + (size_t)(r + 8) * N + c) = v23;
        }
    }
}

// ---------------- GRU step, layer 0 --------------------------------------------
// Grid 128 blocks x 8 output cols; 8 warps split K=1024 -> 128 each; fused gates.
__global__ __launch_bounds__(256)
void gru_step1(int t, const float* __restrict__ U0, const float* __restrict__ b0) {
    const float* h1o = g_h1[t & 1];
    float* h1n = g_h1[(t + 1) & 1];
    int tid = threadIdx.x, warp = tid >> 5, lane = tid & 31;
    int lg = lane >> 2, lt = lane & 3;
    int j0 = blockIdx.x * 8;
    int kb = warp * 128;

    float acc[3][2][4];
#pragma unroll
    for (int g = 0; g < 3; g++)
#pragma unroll
        for (int m = 0; m < 2; m++)
#pragma unroll
            for (int q = 0; q < 4; q++) acc[g][m][q] = 0.0f;

#pragma unroll 4
    for (int ks = 0; ks < 128; ks += 8) {
        int k0 = kb + ks;
        uint32_t aF[2][4];
#pragma unroll
        for (int mt = 0; mt < 2; mt++) {
            int r0 = (mt * 16 + lg) * HH;
            aF[mt][0] = f2tf(h1o[r0 + k0 + lt]);
            aF[mt][1] = f2tf(h1o[r0 + 8 * HH + k0 + lt]);
            aF[mt][2] = f2tf(h1o[r0 + k0 + lt + 4]);
            aF[mt][3] = f2tf(h1o[r0 + 8 * HH + k0 + lt + 4]);
        }
#pragma unroll
        for (int g = 0; g < 3; g++) {
            int c = g * HH + j0 + lg;
            uint32_t b0r = f2tf(U0[(k0 + lt) * G3H + c]);
            uint32_t b1r = f2tf(U0[(k0 + 4 + lt) * G3H + c]);
            mma_tf32(acc[g][0], aF[0], b0r, b1r);
            mma_tf32(acc[g][1], aF[1], b0r, b1r);
        }
    }

    __shared__ float Sp[8][3][32][8];
#pragma unroll
    for (int g = 0; g < 3; g++)
#pragma unroll
        for (int mt = 0; mt < 2; mt++) {
            int rr = mt * 16 + lg;
            Sp[warp][g][rr][lt * 2]         = acc[g][mt][0];
            Sp[warp][g][rr][lt * 2 + 1]     = acc[g][mt][1];
            Sp[warp][g][rr + 8][lt * 2]     = acc[g][mt][2];
            Sp[warp][g][rr + 8][lt * 2 + 1] = acc[g][mt][3];
        }
    __syncthreads();

    int b = tid >> 3, jj = tid & 7;
    int j = j0 + jj;
    float sz = 0.f, sr = 0.f, sh = 0.f;
#pragma unroll
    for (int w = 0; w < 8; w++) {
        sz += Sp[w][0][b][jj];
        sr += Sp[w][1][b][jj];
        sh += Sp[w][2][b][jj];
    }
    const float* gx = g_gx0 + (size_t)(b * TT + t) * G3H;
    const float* bh = b0 + G3H;  // b0[1]
    float z = sigm(gx[j] + sz + bh[j]);
    float r = sigm(gx[HH + j] + sr + bh[HH + j]);
    float hc = tanhf(gx[2 * HH + j] + r * (sh + bh[2 * HH + j]));
    float ho = h1o[b * HH + j];
    h1n[b * HH + j] = z * ho + (1.0f - z) * hc;
}

// ---------------- GRU step, layer 1 (x- and h-gates fused) ---------------------
__global__ __launch_bounds__(256)
void gru_step2(int t, const float* __restrict__ W1, const float* __restrict__ U1,
               const float* __restrict__ b1) {
    const float* h1n = g_h1[(t + 1) & 1];
    const float* h2o = g_h2[t & 1];
    float* h2n = g_h2[(t + 1) & 1];
    int tid = threadIdx.x, warp = tid >> 5, lane = tid & 31;
    int lg = lane >> 2, lt = lane & 3;
    int j0 = blockIdx.x * 8;
    int kb = warp * 128;

    float acc[6][2][4];
#pragma unroll
    for (int g = 0; g < 6; g++)
#pragma unroll
        for (int m = 0; m < 2; m++)
#pragma unroll
            for (int q = 0; q < 4; q++) acc[g][m][q] = 0.0f;

#pragma unroll 2
    for (int ks = 0; ks < 128; ks += 8) {
        int k0 = kb + ks;
        uint32_t aF1[2][4], aF2[2][4];
#pragma unroll
        for (int mt = 0; mt < 2; mt++) {
            int r0 = (mt * 16 + lg) * HH;
            aF1[mt][0] = f2tf(h1n[r0 + k0 + lt]);
            aF1[mt][1] = f2tf(h1n[r0 + 8 * HH + k0 + lt]);
            aF1[mt][2] = f2tf(h1n[r0 + k0 + lt + 4]);
            aF1[mt][3] = f2tf(h1n[r0 + 8 * HH + k0 + lt + 4]);
            aF2[mt][0] = f2tf(h2o[r0 + k0 + lt]);
            aF2[mt][1] = f2tf(h2o[r0 + 8 * HH + k0 + lt]);
            aF2[mt][2] = f2tf(h2o[r0 + k0 + lt + 4]);
            aF2[mt][3] = f2tf(h2o[r0 + 8 * HH + k0 + lt + 4]);
        }
#pragma unroll
        for (int g = 0; g < 3; g++) {
            int c = g * HH + j0 + lg;
            uint32_t bw0 = f2tf(W1[(k0 + lt) * G3H + c]);
            uint32_t bw1 = f2tf(W1[(k0 + 4 + lt) * G3H + c]);
            mma_tf32(acc[g][0], aF1[0], bw0, bw1);
            mma_tf32(acc[g][1], aF1[1], bw0, bw1);
            uint32_t bu0 = f2tf(U1[(k0 + lt) * G3H + c]);
            uint32_t bu1 = f2tf(U1[(k0 + 4 + lt) * G3H + c]);
            mma_tf32(acc[3 + g][0], aF2[0], bu0, bu1);
            mma_tf32(acc[3 + g][1], aF2[1], bu0, bu1);
        }
    }

    // two-stage reduce (keeps static SMEM at 24 KB)
    __shared__ float Sp[4][6][32][8];
    if (warp >= 4) {
#pragma unroll
        for (int g = 0; g < 6; g++)
#pragma unroll
            for (int mt = 0; mt < 2; mt++) {
                int rr = mt * 16 + lg;
                Sp[warp - 4][g][rr][lt * 2]         = acc[g][mt][0];
                Sp[warp - 4][g][rr][lt * 2 + 1]     = acc[g][mt][1];
                Sp[warp - 4][g][rr + 8][lt * 2]     = acc[g][mt][2];
                Sp[warp - 4][g][rr + 8][lt * 2 + 1] = acc[g][mt][3];
            }
    }
    __syncthreads();
    if (warp < 4) {
#pragma unroll
        for (int g = 0; g < 6; g++)
#pragma unroll
            for (int mt = 0; mt < 2; mt++) {
                int rr = mt * 16 + lg;
                Sp[warp][g][rr][lt * 2]         += acc[g][mt][0];
                Sp[warp][g][rr][lt * 2 + 1]     += acc[g][mt][1];
                Sp[warp][g][rr + 8][lt * 2]     += acc[g][mt][2];
                Sp[warp][g][rr + 8][lt * 2 + 1] += acc[g][mt][3];
            }
    }
    __syncthreads();

    int b = tid >> 3, jj = tid & 7;
    int j = j0 + jj;
    float xz = 0.f, xr = 0.f, xh = 0.f, hz = 0.f, hr = 0.f, hhs = 0.f;
#pragma unroll
    for (int w = 0; w < 4; w++) {
        xz += Sp[w][0][b][jj];
        xr += Sp[w][1][b][jj];
        xh += Sp[w][2][b][jj];
        hz += Sp[w][3][b][jj];
        hr += Sp[w][4][b][jj];
        hhs += Sp[w][5][b][jj];
    }
    const float* bx = b1;            // b1[0]
    const float* bh = b1 + G3H;      // b1[1]
    float z = sigm(xz + bx[j] + hz + bh[j]);
    float r = sigm(xr + bx[HH + j] + hr + bh[HH + j]);
    float hc = tanhf(xh + bx[2 * HH + j] + r * (hhs + bh[2 * HH + j]));
    float ho = h2o[b * HH + j];
    float v = z * ho + (1.0f - z) * hc;
    h2n[b * HH + j] = v;
    g_seq[(size_t)(b * TT + t) * HH + j] = v;
}

// ---------------- final hidden-state copy --------------------------------------
__global__ void finalize_hidden(float* __restrict__ out) {
    int i = blockIdx.x * blockDim.x + threadIdx.x;
    if (i < BB * HH)
        out[BTV + i] = g_h1[0][i];
    else if (i < 2 * BB * HH)
        out[BTV + i] = g_h2[0][i - BB * HH];
}

// ---------------- launch -------------------------------------------------------
extern "C" void kernel_launch(void* const* d_in, const int* in_sizes, int n_in,
                              void* d_out, int out_size) {
    (void)in_sizes; (void)n_in; (void)out_size;
    const int*   X   = (const int*)d_in[0];     // int64-or-int32, detected on device
    const float* h0  = (const float*)d_in[1];
    const float* emb = (const float*)d_in[2];
    const float* W0  = (const float*)d_in[3];
    const float* U0  = (const float*)d_in[4];
    const float* b0  = (const float*)d_in[5];
    const float* W1  = (const float*)d_in[6];
    const float* U1  = (const float*)d_in[7];
    const float* b1  = (const float*)d_in[8];
    const float* Wd  = (const float*)d_in[9];
    const float* bd  = (const float*)d_in[10];
    float* out = (float*)d_out;

    detect_tokens<<<1, 1024>>>(X);

    int prep_threads = NROWS * KIN;  // 3,145,728 (covers hidden init too)
    prep_kernel<<<(prep_threads + 255) / 256, 256>>>(h0, emb);

    // gx0 = dec_in @ W0 + b0[0]   (M=2048, N=3072, K=1536)
    gemm_tf32<<<(NROWS / 128) * (G3H / 256), 512>>>(0, W0, b0, nullptr,
                                                    NROWS, G3H, KIN);

    for (int t = 0; t < TT; t++) {
        gru_step1<<<HH / 8, 256>>>(t, U0, b0);
        gru_step2<<<HH / 8, 256>>>(t, W1, U1, b1);
    }

    // logits = seq @ Wd + bd  ->  d_out[0 : B*T*V]   (M=2048, N=32000, K=1024)
    gemm_tf32<<<(NROWS / 128) * (VV / 256), 512>>>(1, Wd, bd, out,
                                                   NROWS, VV, HH);

    finalize_hidden<<<(2 * BB * HH) / 256, 256>>>(out);
}

// round 6
// speedup vs baseline: 1.2376x; 1.2376x over previous
#include <cuda_runtime.h>
#include <cuda_bf16.h>
#include <math.h>
#include <stdint.h>

// Problem constants
#define BB 32
#define TT 64
#define HH 1024
#define EE 512
#define VV 32000
#define NROWS (BB * TT)          // 2048
#define KIN  (EE + HH)           // 1536
#define G3H  (3 * HH)            // 3072
#define NB   128                 // persistent blocks (1/SM, <=148 -> co-resident)
static const size_t BTV = (size_t)BB * TT * VV;  // 65,536,000

// ---------------- device scratch (static; no cudaMalloc anywhere) --------------
__device__ float g_A0[NROWS * KIN];        // dec_in  [2048, 1536]
__device__ float g_gx0[NROWS * G3H];       // x-gates [2048, 3072] (gx0, then gx1)
__device__ float g_h1seq[NROWS * HH];      // h1 per (b,t)  [2048, 1024]
__device__ float g_seq[NROWS * HH];        // h2 per (b,t)  [2048, 1024]
__device__ int   g_tok[NROWS];             // normalized tokens
__device__ unsigned g_bar;                 // grid barrier counter (monotonic per phase)

// ---------------- helpers ------------------------------------------------------
__device__ __forceinline__ uint32_t f2tf(float x) {
    uint32_t u;
    asm("cvt.rna.tf32.f32 %0, %1;" : "=r"(u) : "f"(x));
    return u;
}
__device__ __forceinline__ float f2tff(float x) { return __uint_as_float(f2tf(x)); }

__device__ __forceinline__ void mma_tf32(float c[4], const uint32_t a[4],
                                         uint32_t b0, uint32_t b1) {
    asm volatile(
        "mma.sync.aligned.m16n8k8.row.col.f32.tf32.tf32.f32 "
        "{%0,%1,%2,%3}, {%4,%5,%6,%7}, {%8,%9}, {%0,%1,%2,%3};\n"
        : "+f"(c[0]), "+f"(c[1]), "+f"(c[2]), "+f"(c[3])
        : "r"(a[0]), "r"(a[1]), "r"(a[2]), "r"(a[3]), "r"(b0), "r"(b1));
}

__device__ __forceinline__ float sigm(float x) { return 1.0f / (1.0f + expf(-x)); }

// ---------------- token dtype detect + normalize -------------------------------
__global__ void detect_tokens(const int* __restrict__ Xw) {
    __shared__ int flag;
    int tid = threadIdx.x;
    if (tid == 0) flag = 0;
    __syncthreads();
    if (Xw[2 * tid + 1] != 0) atomicOr(&flag, 1);
    __syncthreads();
    bool is64 = (flag == 0);
    for (int i = tid; i < NROWS; i += 1024)
        g_tok[i] = is64 ? Xw[2 * i] : Xw[i];
}

// ---------------- prep: build dec_in -------------------------------------------
__global__ void prep_kernel(const float* __restrict__ h0, const float* __restrict__ emb) {
    int idx = blockIdx.x * blockDim.x + threadIdx.x;
    if (idx >= NROWS * KIN) return;
    int n = idx / KIN;
    int k = idx - n * KIN;
    float v;
    if (k < EE) {
        v = emb[(size_t)g_tok[n] * EE + k];
    } else {
        int b = n >> 6;                          // n = b*T + t
        v = h0[BB * HH + b * HH + (k - EE)];     // context = h0[1][b]
    }
    g_A0[idx] = v;
}

// ---------------- big tf32 GEMM: C[M,N] = A[M,K] @ B[K,N] + bias ---------------
// sel==0: A=g_A0 -> g_gx0 (gx0).  sel==1: A=g_seq -> Cext (logits).
// sel==2: A=g_h1seq -> g_gx0 (gx1).
__global__ __launch_bounds__(512, 1)
void gemm_tf32(int sel, const float* __restrict__ Bm, const float* __restrict__ bias,
               float* __restrict__ Cext, int M, int N, int K) {
    const float* A = (sel == 0) ? g_A0 : (sel == 1 ? g_seq : g_h1seq);
    float* C = (sel == 1) ? Cext : g_gx0;

    const int BM = 128, BN = 256;
    __shared__ float As[16][BM + 4];
    __shared__ float Bs[16][BN + 4];

    int tid = threadIdx.x;
    int warp = tid >> 5, lane = tid & 31;
    int wm = warp >> 2, wn = warp & 3;
    int lg = lane >> 2, lt = lane & 3;

    int mtiles = M / BM;
    int bm = blockIdx.x % mtiles;
    int bn = blockIdx.x / mtiles;
    int m0 = bm * BM, n0 = bn * BN;

    float acc[2][8][4];
#pragma unroll
    for (int a = 0; a < 2; a++)
#pragma unroll
        for (int b = 0; b < 8; b++)
#pragma unroll
            for (int c = 0; c < 4; c++) acc[a][b][c] = 0.0f;

    for (int k0 = 0; k0 < K; k0 += 16) {
        {
            int m = tid >> 2;
            int kq = (tid & 3) << 2;
            const float4 v = *reinterpret_cast<const float4*>(
                A + (size_t)(m0 + m) * K + k0 + kq);
            As[kq + 0][m] = f2tff(v.x);
            As[kq + 1][m] = f2tff(v.y);
            As[kq + 2][m] = f2tff(v.z);
            As[kq + 3][m] = f2tff(v.w);
        }
#pragma unroll
        for (int p = 0; p < 2; p++) {
            int i = tid + (p << 9);
            int kr = i >> 6;
            int nc = (i & 63) << 2;
            const float4 v = *reinterpret_cast<const float4*>(
                Bm + (size_t)(k0 + kr) * N + n0 + nc);
            Bs[kr][nc + 0] = f2tff(v.x);
            Bs[kr][nc + 1] = f2tff(v.y);
            Bs[kr][nc + 2] = f2tff(v.z);
            Bs[kr][nc + 3] = f2tff(v.w);
        }
        __syncthreads();

#pragma unroll
        for (int kk = 0; kk < 16; kk += 8) {
            uint32_t aF[2][4];
#pragma unroll
            for (int mt = 0; mt < 2; mt++) {
                int mr = wm * 32 + mt * 16 + lg;
                aF[mt][0] = __float_as_uint(As[kk + lt][mr]);
                aF[mt][1] = __float_as_uint(As[kk + lt][mr + 8]);
                aF[mt][2] = __float_as_uint(As[kk + lt + 4][mr]);
                aF[mt][3] = __float_as_uint(As[kk + lt + 4][mr + 8]);
            }
#pragma unroll
            for (int nt = 0; nt < 8; nt++) {
                int nc2 = wn * 64 + nt * 8 + lg;
                uint32_t b0r = __float_as_uint(Bs[kk + lt][nc2]);
                uint32_t b1r = __float_as_uint(Bs[kk + 4 + lt][nc2]);
                mma_tf32(acc[0][nt], aF[0], b0r, b1r);
                mma_tf32(acc[1][nt], aF[1], b0r, b1r);
            }
        }
        __syncthreads();
    }

#pragma unroll
    for (int mt = 0; mt < 2; mt++) {
#pragma unroll
        for (int nt = 0; nt < 8; nt++) {
            int r = m0 + wm * 32 + mt * 16 + lg;
            int c = n0 + wn * 64 + nt * 8 + lt * 2;
            float bv0 = bias[c], bv1 = bias[c + 1];
            float2 v01 = make_float2(acc[mt][nt][0] + bv0, acc[mt][nt][1] + bv1);
            *reinterpret_cast<float2*>(C + (size_t)r * N + c) = v01;
            float2 v23 = make_float2(acc[mt][nt][2] + bv0, acc[mt][nt][3] + bv1);
            *reinterpret_cast<float2*>(C + (size_t)(r + 8) * N + c) = v23;
        }
    }
}

// ---------------- barrier reset -------------------------------------------------
__global__ void reset_bar() { g_bar = 0; }

// ---------------- persistent GRU recurrence ------------------------------------
// One phase = 64 dependent steps of h' = GRU(gx_row, h; U), with U SMEM-resident.
// 128 blocks x 256 threads; block owns 8 h-columns; 8 warps split K=1024.
// SMEM: packed tf32 weights [3][128][32] float2 (98304 B) + reduce Sp (24576 B).
#define RECUR_SMEM (98304 + 24576)

__device__ __forceinline__ void grid_bar_wait(unsigned target) {
    __syncthreads();
    if (threadIdx.x == 0) {
        __threadfence();
        atomicAdd(&g_bar, 1u);
        unsigned v;
        do {
            asm volatile("ld.acquire.gpu.u32 %0, [%1];" : "=r"(v) : "l"(&g_bar));
        } while (v < target);
    }
    __syncthreads();
}

__global__ __launch_bounds__(256, 1)
void gru_recur(int phase, const float* __restrict__ U,
               const float* __restrict__ bh,      // bias row 1 (b[1])
               const float* __restrict__ hinit)   // [32][1024]
{
    extern __shared__ float smem[];
    float2* sW = reinterpret_cast<float2*>(smem);        // [3*128*32] float2
    float*  Sp = smem + 24576;                           // [8][3][32][8] floats

    const float* gx = g_gx0;
    float* seq = phase ? g_seq : g_h1seq;

    int tid = threadIdx.x, warp = tid >> 5, lane = tid & 31;
    int lg = lane >> 2, lt = lane & 3;
    int j0 = blockIdx.x * 8;

    // ---- one-time gather of this block's U slice, tf32-rounded, mma-B-packed --
    for (int p = tid; p < 3 * 128 * 32; p += 256) {
        int l = p & 31;
        int ks = (p >> 5) & 127;
        int g = p >> 12;
        int plt = l & 3, plg = l >> 2;
        int col = g * HH + j0 + plg;
        int k = ks * 8 + plt;
        sW[p] = make_float2(f2tff(U[(size_t)k * G3H + col]),
                            f2tff(U[(size_t)(k + 4) * G3H + col]));
    }
    __syncthreads();

    for (int t = 0; t < TT; t++) {
        const float* hp;
        int hstride;
        if (t == 0) { hp = hinit; hstride = HH; }
        else        { hp = seq + (size_t)(t - 1) * HH; hstride = TT * HH; }

        float acc[3][2][4];
#pragma unroll
        for (int g = 0; g < 3; g++)
#pragma unroll
            for (int m = 0; m < 2; m++)
#pragma unroll
                for (int q = 0; q < 4; q++) acc[g][m][q] = 0.0f;

#pragma unroll 4
        for (int ks = 0; ks < 16; ks++) {
            int k0 = warp * 128 + ks * 8;
            uint32_t aF[2][4];
#pragma unroll
            for (int mt = 0; mt < 2; mt++) {
                int rb = mt * 16 + lg;
                aF[mt][0] = f2tf(hp[rb * hstride + k0 + lt]);
                aF[mt][1] = f2tf(hp[(rb + 8) * hstride + k0 + lt]);
                aF[mt][2] = f2tf(hp[rb * hstride + k0 + lt + 4]);
                aF[mt][3] = f2tf(hp[(rb + 8) * hstride + k0 + lt + 4]);
            }
#pragma unroll
            for (int g = 0; g < 3; g++) {
                float2 w = sW[g * 4096 + (warp * 16 + ks) * 32 + lane];
                mma_tf32(acc[g][0], aF[0], __float_as_uint(w.x), __float_as_uint(w.y));
                mma_tf32(acc[g][1], aF[1], __float_as_uint(w.x), __float_as_uint(w.y));
            }
        }

        // cross-warp reduce (K was split over 8 warps)
#pragma unroll
        for (int g = 0; g < 3; g++)
#pragma unroll
            for (int mt = 0; mt < 2; mt++) {
                int rr = mt * 16 + lg;
                float* base = Sp + ((warp * 3 + g) * 32) * 8;
                base[rr * 8 + lt * 2]           = acc[g][mt][0];
                base[rr * 8 + lt * 2 + 1]       = acc[g][mt][1];
                base[(rr + 8) * 8 + lt * 2]     = acc[g][mt][2];
                base[(rr + 8) * 8 + lt * 2 + 1] = acc[g][mt][3];
            }
        __syncthreads();

        int b = tid >> 3, jj = tid & 7;
        int j = j0 + jj;
        float sz = 0.f, sr = 0.f, sh = 0.f;
#pragma unroll
        for (int w = 0; w < 8; w++) {
            const float* base = Sp + (w * 3 * 32) * 8;
            sz += base[(0 * 32 + b) * 8 + jj];
            sr += base[(1 * 32 + b) * 8 + jj];
            sh += base[(2 * 32 + b) * 8 + jj];
        }
        const float* gxr = gx + (size_t)(b * TT + t) * G3H;
        float z = sigm(gxr[j] + sz + bh[j]);
        float r = sigm(gxr[HH + j] + sr + bh[HH + j]);
        float hc = tanhf(gxr[2 * HH + j] + r * (sh + bh[2 * HH + j]));
        float ho = hp[b * hstride + j];
        float v = z * ho + (1.0f - z) * hc;
        seq[(size_t)(b * TT + t) * HH + j] = v;

        if (t + 1 < TT)
            grid_bar_wait((unsigned)(t + 1) * NB);
        else
            __syncthreads();  // protect Sp is moot on last iter; kernel ends
    }
}

// ---------------- final hidden-state copy --------------------------------------
__global__ void finalize_hidden(float* __restrict__ out) {
    int i = blockIdx.x * blockDim.x + threadIdx.x;
    if (i < BB * HH) {
        int b = i >> 10, j = i & 1023;
        out[BTV + i] = g_h1seq[(size_t)(b * TT + (TT - 1)) * HH + j];
    } else if (i < 2 * BB * HH) {
        int k = i - BB * HH;
        int b = k >> 10, j = k & 1023;
        out[BTV + i] = g_seq[(size_t)(b * TT + (TT - 1)) * HH + j];
    }
}

// ---------------- launch -------------------------------------------------------
extern "C" void kernel_launch(void* const* d_in, const int* in_sizes, int n_in,
                              void* d_out, int out_size) {
    (void)in_sizes; (void)n_in; (void)out_size;
    const int*   X   = (const int*)d_in[0];
    const float* h0  = (const float*)d_in[1];
    const float* emb = (const float*)d_in[2];
    const float* W0  = (const float*)d_in[3];
    const float* U0  = (const float*)d_in[4];
    const float* b0  = (const float*)d_in[5];
    const float* W1  = (const float*)d_in[6];
    const float* U1  = (const float*)d_in[7];
    const float* b1  = (const float*)d_in[8];
    const float* Wd  = (const float*)d_in[9];
    const float* bd  = (const float*)d_in[10];
    float* out = (float*)d_out;

    static bool attr_done = false;
    if (!attr_done) {
        cudaFuncSetAttribute(gru_recur, cudaFuncAttributeMaxDynamicSharedMemorySize,
                             RECUR_SMEM);
        attr_done = true;
    }

    detect_tokens<<<1, 1024>>>(X);
    prep_kernel<<<(NROWS * KIN + 255) / 256, 256>>>(h0, emb);

    // gx0 = dec_in @ W0 + b0[0]   (M=2048, N=3072, K=1536)
    gemm_tf32<<<(NROWS / 128) * (G3H / 256), 512>>>(0, W0, b0, nullptr,
                                                    NROWS, G3H, KIN);

    // phase A: layer-0 recurrence (persistent, 64 internal steps)
    reset_bar<<<1, 1>>>();
    gru_recur<<<NB, 256, RECUR_SMEM>>>(0, U0, b0 + G3H, h0);

    // gx1 = h1_seq @ W1 + b1[0]   (M=2048, N=3072, K=1024) — hoisted out of chain
    gemm_tf32<<<(NROWS / 128) * (G3H / 256), 512>>>(2, W1, b1, nullptr,
                                                    NROWS, G3H, HH);

    // phase B: layer-1 recurrence
    reset_bar<<<1, 1>>>();
    gru_recur<<<NB, 256, RECUR_SMEM>>>(1, U1, b1 + G3H, h0 + BB * HH);

    // logits = seq @ Wd + bd  ->  d_out[0 : B*T*V]   (M=2048, N=32000, K=1024)
    gemm_tf32<<<(NROWS / 128) * (VV / 256), 512>>>(1, Wd, bd, out,
                                                   NROWS, VV, HH);

    finalize_hidden<<<(2 * BB * HH + 255) / 256, 256>>>(out);
}

// round 9
// speedup vs baseline: 1.8313x; 1.4797x over previous
#include <cuda_runtime.h>
#include <cuda_bf16.h>
#include <math.h>
#include <stdint.h>

// Problem constants
#define BB 32
#define TT 64
#define HH 1024
#define EE 512
#define VV 32000
#define NROWS (BB * TT)          // 2048
#define KIN  (EE + HH)           // 1536
#define G3H  (3 * HH)            // 3072
#define NB   128                 // persistent blocks (1/SM, co-resident)
static const size_t BTV = (size_t)BB * TT * VV;  // 65,536,000

// ---------------- device scratch (static; no cudaMalloc anywhere) --------------
__device__ __align__(16) float g_A0[NROWS * KIN];     // dec_in  [2048, 1536]
__device__ __align__(16) float g_gx0[NROWS * G3H];    // x-gates [2048, 3072]
__device__ __align__(16) float g_h1seq[NROWS * HH];   // h1 per (b,t)
__device__ __align__(16) float g_seq[NROWS * HH];     // h2 per (b,t)
__device__ __align__(16) float g_hp[2][BB * HH];      // ping-pong packed h (tf32)
__device__ __align__(16) float g_hp0A[BB * HH];       // packed h0[0]
__device__ __align__(16) float g_hp0B[BB * HH];       // packed h0[1]
__device__ int   g_tok[NROWS];                        // normalized tokens
__device__ unsigned g_bar;                            // monotonic barrier counter

// ---------------- helpers ------------------------------------------------------
__device__ __forceinline__ uint32_t f2tf(float x) {
    uint32_t u;
    asm("cvt.rna.tf32.f32 %0, %1;" : "=r"(u) : "f"(x));
    return u;
}
__device__ __forceinline__ float f2tff(float x) { return __uint_as_float(f2tf(x)); }

__device__ __forceinline__ void mma_tf32(float c[4], uint32_t a0, uint32_t a1,
                                         uint32_t a2, uint32_t a3,
                                         uint32_t b0, uint32_t b1) {
    asm volatile(
        "mma.sync.aligned.m16n8k8.row.col.f32.tf32.tf32.f32 "
        "{%0,%1,%2,%3}, {%4,%5,%6,%7}, {%8,%9}, {%0,%1,%2,%3};\n"
        : "+f"(c[0]), "+f"(c[1]), "+f"(c[2]), "+f"(c[3])
        : "r"(a0), "r"(a1), "r"(a2), "r"(a3), "r"(b0), "r"(b1));
}

__device__ __forceinline__ float2 ldcg2(const float* p) {
    float2 v;
    asm volatile("ld.global.cg.v2.f32 {%0,%1}, [%2];"
                 : "=f"(v.x), "=f"(v.y) : "l"(p));
    return v;
}

__device__ __forceinline__ float sigm(float x) { return 1.0f / (1.0f + expf(-x)); }

// packed index for h value (b, k): within each 8-k group, order [0,4,1,5,2,6,3,7]
__device__ __forceinline__ int packidx(int b, int k) {
    return (k >> 3) * 256 + b * 8 + ((k & 3) * 2 + ((k >> 2) & 1));
}

// ---------------- token detect + barrier reset + h0 pack -----------------------
__global__ void detect_tokens(const int* __restrict__ Xw, const float* __restrict__ h0) {
    __shared__ int flag;
    int tid = threadIdx.x;
    if (tid == 0) { flag = 0; g_bar = 0; }
    __syncthreads();
    if (Xw[2 * tid + 1] != 0) atomicOr(&flag, 1);
    __syncthreads();
    bool is64 = (flag == 0);
    for (int i = tid; i < NROWS; i += 1024)
        g_tok[i] = is64 ? Xw[2 * i] : Xw[i];
    // pack h0[0] and h0[1] into mma-fragment order, tf32-rounded
    for (int i = tid; i < BB * HH; i += 1024) {
        int b = i >> 10, k = i & 1023;
        int d = packidx(b, k);
        g_hp0A[d] = f2tff(h0[b * HH + k]);
        g_hp0B[d] = f2tff(h0[BB * HH + b * HH + k]);
    }
}

// ---------------- prep: build dec_in -------------------------------------------
__global__ void prep_kernel(const float* __restrict__ h0, const float* __restrict__ emb) {
    int idx = blockIdx.x * blockDim.x + threadIdx.x;
    if (idx >= NROWS * KIN) return;
    int n = idx / KIN;
    int k = idx - n * KIN;
    float v;
    if (k < EE) {
        v = emb[(size_t)g_tok[n] * EE + k];
    } else {
        int b = n >> 6;                          // n = b*T + t
        v = h0[BB * HH + b * HH + (k - EE)];     // context = h0[1][b]
    }
    g_A0[idx] = v;
}

// ---------------- big tf32 GEMM, register-staged double buffered ---------------
// Dynamic smem: As[2][16][132] + Bs[2][16][260]  (50176 B)
#define GEMM_SMEM ((2 * 16 * 132 + 2 * 16 * 260) * 4)
// sel==0: A=g_A0 -> g_gx0.  sel==1: A=g_seq -> Cext.  sel==2: A=g_h1seq -> g_gx0.
__global__ __launch_bounds__(512, 1)
void gemm_tf32(int sel, const float* __restrict__ Bm, const float* __restrict__ bias,
               float* __restrict__ Cext, int M, int N, int K) {
    const float* A = (sel == 0) ? g_A0 : (sel == 1 ? g_seq : g_h1seq);
    float* C = (sel == 1) ? Cext : g_gx0;

    extern __shared__ float gsm[];
    float (*As)[16][132] = reinterpret_cast<float(*)[16][132]>(gsm);
    float (*Bs)[16][260] = reinterpret_cast<float(*)[16][260]>(gsm + 2 * 16 * 132);

    int tid = threadIdx.x;
    int warp = tid >> 5, lane = tid & 31;
    int wm = warp >> 2, wn = warp & 3;
    int lg = lane >> 2, lt = lane & 3;

    int mtiles = M / 128;
    int bm = blockIdx.x % mtiles;
    int bn = blockIdx.x / mtiles;
    int m0 = bm * 128, n0 = bn * 256;

    float acc[2][8][4];
#pragma unroll
    for (int a = 0; a < 2; a++)
#pragma unroll
        for (int b = 0; b < 8; b++)
#pragma unroll
            for (int c = 0; c < 4; c++) acc[a][b][c] = 0.0f;

    int am = tid >> 2, akq = (tid & 3) << 2;
    const float* Aptr = A + (size_t)(m0 + am) * K + akq;
    int brr = tid >> 6, bcc = (tid & 63) << 2;
    const float* Bptr = Bm + (size_t)brr * N + n0 + bcc;

    int Tn = K / 16;
    float4 ra, rb0, rb1;
    ra  = *reinterpret_cast<const float4*>(Aptr);
    rb0 = *reinterpret_cast<const float4*>(Bptr);
    rb1 = *reinterpret_cast<const float4*>(Bptr + (size_t)8 * N);

    int s = 0;
    for (int tI = 0; tI < Tn; tI++) {
        // stage current regs -> smem[s], tf32-rounded
        As[s][akq + 0][am] = f2tff(ra.x);
        As[s][akq + 1][am] = f2tff(ra.y);
        As[s][akq + 2][am] = f2tff(ra.z);
        As[s][akq + 3][am] = f2tff(ra.w);
        Bs[s][brr][bcc + 0] = f2tff(rb0.x);
        Bs[s][brr][bcc + 1] = f2tff(rb0.y);
        Bs[s][brr][bcc + 2] = f2tff(rb0.z);
        Bs[s][brr][bcc + 3] = f2tff(rb0.w);
        Bs[s][brr + 8][bcc + 0] = f2tff(rb1.x);
        Bs[s][brr + 8][bcc + 1] = f2tff(rb1.y);
        Bs[s][brr + 8][bcc + 2] = f2tff(rb1.z);
        Bs[s][brr + 8][bcc + 3] = f2tff(rb1.w);
        __syncthreads();

        // prefetch next tile into regs (overlaps with compute below)
        if (tI + 1 < Tn) {
            ra  = *reinterpret_cast<const float4*>(Aptr + (size_t)(tI + 1) * 16);
            rb0 = *reinterpret_cast<const float4*>(Bptr + (size_t)(tI + 1) * 16 * N);
            rb1 = *reinterpret_cast<const float4*>(Bptr + (size_t)((tI + 1) * 16 + 8) * N);
        }

        // compute from smem[s]
#pragma unroll
        for (int kk = 0; kk < 16; kk += 8) {
            uint32_t aF[2][4];
#pragma unroll
            for (int mt = 0; mt < 2; mt++) {
                int mr = wm * 32 + mt * 16 + lg;
                aF[mt][0] = __float_as_uint(As[s][kk + lt][mr]);
                aF[mt][1] = __float_as_uint(As[s][kk + lt][mr + 8]);
                aF[mt][2] = __float_as_uint(As[s][kk + lt + 4][mr]);
                aF[mt][3] = __float_as_uint(As[s][kk + lt + 4][mr + 8]);
            }
#pragma unroll
            for (int nt = 0; nt < 8; nt++) {
                int nc2 = wn * 64 + nt * 8 + lg;
                uint32_t b0r = __float_as_uint(Bs[s][kk + lt][nc2]);
                uint32_t b1r = __float_as_uint(Bs[s][kk + 4 + lt][nc2]);
                mma_tf32(acc[0][nt], aF[0][0], aF[0][1], aF[0][2], aF[0][3], b0r, b1r);
                mma_tf32(acc[1][nt], aF[1][0], aF[1][1], aF[1][2], aF[1][3], b0r, b1r);
            }
        }
        s ^= 1;
    }

#pragma unroll
    for (int mt = 0; mt < 2; mt++) {
#pragma unroll
        for (int nt = 0; nt < 8; nt++) {
            int r = m0 + wm * 32 + mt * 16 + lg;
            int c = n0 + wn * 64 + nt * 8 + lt * 2;
            float bv0 = bias[c], bv1 = bias[c + 1];
            float2 v01 = make_float2(acc[mt][nt][0] + bv0, acc[mt][nt][1] + bv1);
            *reinterpret_cast<float2*>(C + (size_t)r * N + c) = v01;
            float2 v23 = make_float2(acc[mt][nt][2] + bv0, acc[mt][nt][3] + bv1);
            *reinterpret_cast<float2*>(C + (size_t)(r + 8) * N + c) = v23;
        }
    }
}

// ---------------- persistent GRU recurrence ------------------------------------
// SMEM: packed tf32 weights (98304 B) + reduce scratch Sp (24576 B).
#define RECUR_SMEM (98304 + 24576)

__device__ __forceinline__ void grid_bar(unsigned target) {
    __syncthreads();
    if (threadIdx.x == 0) {
        __threadfence();
        atomicAdd(&g_bar, 1u);
        unsigned v;
        do {
            asm volatile("ld.acquire.gpu.u32 %0, [%1];" : "=r"(v) : "l"(&g_bar));
        } while (v < target);
    }
    __syncthreads();
}

// load one 8-k group of packed A fragments (4x LDG.64, fully coalesced)
__device__ __forceinline__ void ld_frag(const float* cur, int kg, int lg, int lt,
                                        float2 fr[4]) {
    const float* base = cur + kg * 256 + lt * 2;
    fr[0] = ldcg2(base + lg * 8);
    fr[1] = ldcg2(base + (lg + 8) * 8);
    fr[2] = ldcg2(base + (lg + 16) * 8);
    fr[3] = ldcg2(base + (lg + 24) * 8);
}

// phase 0: U=U0, seq=g_h1seq, s0p=g_hp0A. phase 1: U=U1, seq=g_seq, s0p=g_hp0B.
// NOTE: all __device__ globals resolved IN DEVICE CODE (host-passed device-symbol
// addresses are host shadow addresses on ATS systems -> silent wrong memory).
__global__ __launch_bounds__(256, 1)
void gru_recur(int base, int phase, const float* __restrict__ U,
               const float* __restrict__ bh,      // bias row 1 (b[1])
               const float* __restrict__ hinit)   // [32][1024] row-major (exact)
{
    extern __shared__ float smem[];
    float2* sW = reinterpret_cast<float2*>(smem);        // [3*128*32] float2
    float*  sWf = smem;                                  // scalar view
    float*  Sp = smem + 24576;                           // [8][3][32][8]

    float* seq = phase ? g_seq : g_h1seq;
    const float* s0p = phase ? g_hp0B : g_hp0A;

    int tid = threadIdx.x, warp = tid >> 5, lane = tid & 31;
    int lg = lane >> 2, lt = lane & 3;
    int j0 = blockIdx.x * 8;

    // one-time weight gather: coalesced reads (4 full sectors / LDG)
    for (int e = tid; e < 3 * 8192; e += 256) {
        int g = e >> 13;
        int r = e & 8191;
        int k = r >> 3;
        int jj = r & 7;
        float w = U[(size_t)k * G3H + g * HH + j0 + jj];
        int wwarp = k >> 7, kk = k & 127, ks = kk >> 3, c = kk & 7;
        int wlt = c & 3, half = c >> 2;
        int wlane = jj * 4 + wlt;
        sWf[(g * 4096 + (wwarp * 16 + ks) * 32 + wlane) * 2 + half] = f2tff(w);
    }
    __syncthreads();

    for (int t = 0; t < TT; t++) {
        const float* cur = (t == 0) ? s0p : g_hp[t & 1];
        float* nxt = g_hp[(t + 1) & 1];

        float acc[3][2][4];
#pragma unroll
        for (int g = 0; g < 3; g++)
#pragma unroll
            for (int m = 0; m < 2; m++)
#pragma unroll
                for (int q = 0; q < 4; q++) acc[g][m][q] = 0.0f;

        // depth-2 software pipeline over 16 k-groups
        float2 fr[3][4];
        ld_frag(cur, warp * 16 + 0, lg, lt, fr[0]);
        ld_frag(cur, warp * 16 + 1, lg, lt, fr[1]);
#pragma unroll
        for (int ks = 0; ks < 16; ks++) {
            if (ks + 2 < 16) ld_frag(cur, warp * 16 + ks + 2, lg, lt, fr[(ks + 2) % 3]);
            const float2* f = fr[ks % 3];
            uint32_t a00 = __float_as_uint(f[0].x), a01 = __float_as_uint(f[1].x);
            uint32_t a02 = __float_as_uint(f[0].y), a03 = __float_as_uint(f[1].y);
            uint32_t a10 = __float_as_uint(f[2].x), a11 = __float_as_uint(f[3].x);
            uint32_t a12 = __float_as_uint(f[2].y), a13 = __float_as_uint(f[3].y);
#pragma unroll
            for (int g = 0; g < 3; g++) {
                float2 w = sW[g * 4096 + (warp * 16 + ks) * 32 + lane];
                uint32_t b0 = __float_as_uint(w.x), b1 = __float_as_uint(w.y);
                mma_tf32(acc[g][0], a00, a01, a02, a03, b0, b1);
                mma_tf32(acc[g][1], a10, a11, a12, a13, b0, b1);
            }
        }

        // cross-warp K reduction via SMEM
#pragma unroll
        for (int g = 0; g < 3; g++)
#pragma unroll
            for (int mt = 0; mt < 2; mt++) {
                int rr = mt * 16 + lg;
                float* sb = Sp + ((warp * 3 + g) * 32) * 8;
                sb[rr * 8 + lt * 2]           = acc[g][mt][0];
                sb[rr * 8 + lt * 2 + 1]       = acc[g][mt][1];
                sb[(rr + 8) * 8 + lt * 2]     = acc[g][mt][2];
                sb[(rr + 8) * 8 + lt * 2 + 1] = acc[g][mt][3];
            }
        __syncthreads();

        int b = tid >> 3, jj = tid & 7;
        int j = j0 + jj;
        float sz = 0.f, sr = 0.f, sh = 0.f;
#pragma unroll
        for (int w = 0; w < 8; w++) {
            const float* sb = Sp + (w * 3 * 32) * 8;
            sz += sb[(0 * 32 + b) * 8 + jj];
            sr += sb[(1 * 32 + b) * 8 + jj];
            sh += sb[(2 * 32 + b) * 8 + jj];
        }
        const float* gxr = g_gx0 + (size_t)(b * TT + t) * G3H;
        float z = sigm(gxr[j] + sz + bh[j]);
        float r = sigm(gxr[HH + j] + sr + bh[HH + j]);
        float hc = tanhf(gxr[2 * HH + j] + r * (sh + bh[2 * HH + j]));
        float ho = (t == 0) ? hinit[b * HH + j]
                            : seq[((size_t)b * TT + t - 1) * HH + j];
        float v = z * ho + (1.0f - z) * hc;
        seq[((size_t)b * TT + t) * HH + j] = v;                 // exact
        nxt[blockIdx.x * 256 + b * 8 + ((jj & 3) * 2 + (jj >> 2))] = f2tff(v);  // packed

        if (t + 1 < TT) grid_bar((unsigned)(base + t + 1) * NB);
    }
}

// ---------------- final hidden-state copy --------------------------------------
__global__ void finalize_hidden(float* __restrict__ out) {
    int i = blockIdx.x * blockDim.x + threadIdx.x;
    if (i < BB * HH) {
        int b = i >> 10, j = i & 1023;
        out[BTV + i] = g_h1seq[((size_t)b * TT + (TT - 1)) * HH + j];
    } else if (i < 2 * BB * HH) {
        int k = i - BB * HH;
        int b = k >> 10, j = k & 1023;
        out[BTV + i] = g_seq[((size_t)b * TT + (TT - 1)) * HH + j];
    }
}

// ---------------- launch -------------------------------------------------------
extern "C" void kernel_launch(void* const* d_in, const int* in_sizes, int n_in,
                              void* d_out, int out_size) {
    (void)in_sizes; (void)n_in; (void)out_size;
    const int*   X   = (const int*)d_in[0];
    const float* h0  = (const float*)d_in[1];
    const float* emb = (const float*)d_in[2];
    const float* W0  = (const float*)d_in[3];
    const float* U0  = (const float*)d_in[4];
    const float* b0  = (const float*)d_in[5];
    const float* W1  = (const float*)d_in[6];
    const float* U1  = (const float*)d_in[7];
    const float* b1  = (const float*)d_in[8];
    const float* Wd  = (const float*)d_in[9];
    const float* bd  = (const float*)d_in[10];
    float* out = (float*)d_out;

    cudaFuncSetAttribute(gru_recur, cudaFuncAttributeMaxDynamicSharedMemorySize,
                         RECUR_SMEM);
    cudaFuncSetAttribute(gemm_tf32, cudaFuncAttributeMaxDynamicSharedMemorySize,
                         GEMM_SMEM);

    // launch index:                                        ncu -s 5 target
    detect_tokens<<<1, 1024>>>(X, h0);                      // 0
    prep_kernel<<<(NROWS * KIN + 255) / 256, 256>>>(h0, emb); // 1

    // gx0 = dec_in @ W0 + b0[0]   (M=2048, N=3072, K=1536)
    gemm_tf32<<<(NROWS / 128) * (G3H / 256), 512, GEMM_SMEM>>>(
        0, W0, b0, nullptr, NROWS, G3H, KIN);               // 2

    // phase A: layer-0 recurrence (seq/s0p resolved in-kernel)
    gru_recur<<<NB, 256, RECUR_SMEM>>>(0, 0, U0, b0 + G3H, h0); // 3

    // gx1 = h1_seq @ W1 + b1[0]   (M=2048, N=3072, K=1024)
    gemm_tf32<<<(NROWS / 128) * (G3H / 256), 512, GEMM_SMEM>>>(
        2, W1, b1, nullptr, NROWS, G3H, HH);                // 4

    // phase B: layer-1 recurrence  (<- ncu -s 5 captures this one)
    gru_recur<<<NB, 256, RECUR_SMEM>>>(63, 1, U1, b1 + G3H, h0 + BB * HH); // 5

    // logits = seq @ Wd + bd  ->  d_out[0 : B*T*V]   (M=2048, N=32000, K=1024)
    gemm_tf32<<<(NROWS / 128) * (VV / 256), 512, GEMM_SMEM>>>(
        1, Wd, bd, out, NROWS, VV, HH);                     // 6

    finalize_hidden<<<(2 * BB * HH + 255) / 256, 256>>>(out); // 7
}